// round 2
// baseline (speedup 1.0000x reference)
#include <cuda_runtime.h>

#define NODELEN 10
#define DEG 32
#define MAXN 200000
#define PAD 16   // padded row length (64B, one aligned half-line)

// Allocation-free scratch: padded feature table and padded hop-1 table.
__device__ float g_feat[(size_t)MAXN * PAD];
__device__ float g_h1[(size_t)MAXN * PAD];

// ---------------------------------------------------------------------------
// Prep: pad features [N,10] -> g_feat [N,16], zero padding.
// ---------------------------------------------------------------------------
__global__ __launch_bounds__(256) void pad_features_kernel(
    const float* __restrict__ features, int N)
{
    int idx = blockIdx.x * blockDim.x + threadIdx.x;
    int total = N * PAD;
    if (idx >= total) return;
    int n = idx >> 4;
    int k = idx & 15;
    g_feat[idx] = (k < NODELEN) ? features[(size_t)n * NODELEN + k] : 0.f;
}

// ---------------------------------------------------------------------------
// Gather-mean core: one warp per node. 4 lanes per row (float4 each = 64B row),
// 8 rows per LDG.128 instruction -> 4 load instructions per node, exactly one
// 128B line touched per gathered row.
// Returns: every lane holds the 32-row sum for its quad j = lane&3 in acc4.
// ---------------------------------------------------------------------------
__device__ __forceinline__ float4 gather_sum(const float* __restrict__ table,
                                             int myNb, int lane)
{
    int rg = lane >> 2;   // row group 0..7
    int j  = lane & 3;    // quad within row
    float4 acc = make_float4(0.f, 0.f, 0.f, 0.f);
#pragma unroll
    for (int i = 0; i < 4; i++) {
        int nb = __shfl_sync(0xffffffffu, myNb, i * 8 + rg);
        float4 v = *reinterpret_cast<const float4*>(table + (size_t)nb * PAD + j * 4);
        acc.x += v.x; acc.y += v.y; acc.z += v.z; acc.w += v.w;
    }
    // xor-butterfly over row groups (bits 2..4): all lanes end with the
    // full 32-row sum for their own quad j.
#pragma unroll
    for (int off = 4; off < 32; off <<= 1) {
        acc.x += __shfl_xor_sync(0xffffffffu, acc.x, off);
        acc.y += __shfl_xor_sync(0xffffffffu, acc.y, off);
        acc.z += __shfl_xor_sync(0xffffffffu, acc.z, off);
        acc.w += __shfl_xor_sync(0xffffffffu, acc.w, off);
    }
    return acc;
}

// ---------------------------------------------------------------------------
// Hop 1: h1 = mean(features[adj]), col 0 zeroed; written padded to g_h1.
// ---------------------------------------------------------------------------
__global__ __launch_bounds__(256) void hop1_kernel(
    const int* __restrict__ adj, int N)
{
    int warp = (blockIdx.x * blockDim.x + threadIdx.x) >> 5;
    int lane = threadIdx.x & 31;
    if (warp >= N) return;

    int myNb = adj[warp * DEG + lane];
    float4 acc = gather_sum(g_feat, myNb, lane);

    if (lane < 4) {
        float4 v;
        v.x = acc.x * (1.f / 32.f);
        v.y = acc.y * (1.f / 32.f);
        v.z = acc.z * (1.f / 32.f);
        v.w = acc.w * (1.f / 32.f);
        if (lane == 0) v.x = 0.f;                 // h1[:,0] = 0
        // quad 2 dims 10,11 and quad 3 dims 12..15 come from zero padding -> stay 0
        *reinterpret_cast<float4*>(g_h1 + (size_t)warp * PAD + lane * 4) = v;
    }
}

// ---------------------------------------------------------------------------
// Hop 2 + embedding: agg = mean(h1[adj]) (col0 zero);
// emb = [features(col0=0) | agg], written to d_out.
// ---------------------------------------------------------------------------
__global__ __launch_bounds__(256) void hop2_emb_kernel(
    const int* __restrict__ adj, float* __restrict__ emb, int N)
{
    int warp = (blockIdx.x * blockDim.x + threadIdx.x) >> 5;
    int lane = threadIdx.x & 31;
    if (warp >= N) return;

    int myNb = adj[warp * DEG + lane];
    float4 acc = gather_sum(g_h1, myNb, lane);

    // self features for lanes 0..9 (coalesced 40B from one line)
    float featval = 0.f;
    if (lane > 0 && lane < NODELEN)
        featval = g_feat[(size_t)warp * PAD + lane];

    // spread agg quads to lanes 10..19 (uniform shfl participation)
    int d   = lane - 10;
    int src = (d >> 2) & 7;
    float c0 = __shfl_sync(0xffffffffu, acc.x, src);
    float c1 = __shfl_sync(0xffffffffu, acc.y, src);
    float c2 = __shfl_sync(0xffffffffu, acc.z, src);
    float c3 = __shfl_sync(0xffffffffu, acc.w, src);

    if (lane < 20) {
        float val;
        if (lane < 10) {
            val = featval;
        } else {
            int c = d & 3;
            float a = (c == 0) ? c0 : (c == 1) ? c1 : (c == 2) ? c2 : c3;
            val = a * (1.f / 32.f);
            if (d == 0) val = 0.f;                // emb[:,NODELEN] = 0
        }
        emb[(size_t)warp * (2 * NODELEN) + lane] = val;
    }
}

// ---------------------------------------------------------------------------
// MLP autoencoder: thread-per-node, all weights (1075 floats) in shared mem.
// ---------------------------------------------------------------------------
__global__ __launch_bounds__(128) void mlp_kernel(
    const float* __restrict__ emb,
    const float* __restrict__ We1, const float* __restrict__ be1,
    const float* __restrict__ We2, const float* __restrict__ be2,
    const float* __restrict__ We3, const float* __restrict__ be3,
    const float* __restrict__ Wd1, const float* __restrict__ bd1,
    const float* __restrict__ Wd2, const float* __restrict__ bd2,
    const float* __restrict__ Wd3, const float* __restrict__ bd3,
    float* __restrict__ enc_out, float* __restrict__ dec_out, int N)
{
    __shared__ float s[1075];
    {
        const float* srcs[12] = {We1, be1, We2, be2, We3, be3,
                                 Wd1, bd1, Wd2, bd2, Wd3, bd3};
        const int sz[12] = {300, 15, 150, 10, 50, 5, 50, 10, 150, 15, 300, 20};
        int off = 0;
        for (int a = 0; a < 12; a++) {
            for (int k = threadIdx.x; k < sz[a]; k += blockDim.x)
                s[off + k] = srcs[a][k];
            off += sz[a];
        }
    }
    __syncthreads();

    int n = blockIdx.x * blockDim.x + threadIdx.x;
    if (n >= N) return;

    const float* sWe1 = s;          const float* sbe1 = s + 300;
    const float* sWe2 = s + 315;    const float* sbe2 = s + 465;
    const float* sWe3 = s + 475;    const float* sbe3 = s + 525;
    const float* sWd1 = s + 530;    const float* sbd1 = s + 580;
    const float* sWd2 = s + 590;    const float* sbd2 = s + 740;
    const float* sWd3 = s + 755;    const float* sbd3 = s + 1055;

    float x[20];
    const float4* e4 = (const float4*)(emb + (size_t)n * 20);
#pragma unroll
    for (int i = 0; i < 5; i++) {
        float4 t = e4[i];
        x[4 * i + 0] = t.x; x[4 * i + 1] = t.y;
        x[4 * i + 2] = t.z; x[4 * i + 3] = t.w;
    }

    float h1v[15];
#pragma unroll
    for (int i = 0; i < 15; i++) {
        float a = sbe1[i];
#pragma unroll
        for (int j = 0; j < 20; j++) a = fmaf(sWe1[i * 20 + j], x[j], a);
        h1v[i] = fmaxf(a, 0.f);
    }

    float h2v[10];
#pragma unroll
    for (int i = 0; i < 10; i++) {
        float a = sbe2[i];
#pragma unroll
        for (int j = 0; j < 15; j++) a = fmaf(sWe2[i * 15 + j], h1v[j], a);
        h2v[i] = fmaxf(a, 0.f);
    }

    float ev[5];
#pragma unroll
    for (int i = 0; i < 5; i++) {
        float a = sbe3[i];
#pragma unroll
        for (int j = 0; j < 10; j++) a = fmaf(sWe3[i * 10 + j], h2v[j], a);
        ev[i] = a;
    }
#pragma unroll
    for (int i = 0; i < 5; i++) enc_out[(size_t)n * 5 + i] = ev[i];

    float d1v[10];
#pragma unroll
    for (int i = 0; i < 10; i++) {
        float a = sbd1[i];
#pragma unroll
        for (int j = 0; j < 5; j++) a = fmaf(sWd1[i * 5 + j], ev[j], a);
        d1v[i] = fmaxf(a, 0.f);
    }

    float d2v[15];
#pragma unroll
    for (int i = 0; i < 15; i++) {
        float a = sbd2[i];
#pragma unroll
        for (int j = 0; j < 10; j++) a = fmaf(sWd2[i * 10 + j], d1v[j], a);
        d2v[i] = fmaxf(a, 0.f);
    }

    float dv[20];
#pragma unroll
    for (int i = 0; i < 20; i++) {
        float a = sbd3[i];
#pragma unroll
        for (int j = 0; j < 15; j++) a = fmaf(sWd3[i * 15 + j], d2v[j], a);
        dv[i] = a;
    }
    float4* o4 = (float4*)(dec_out + (size_t)n * 20);
#pragma unroll
    for (int i = 0; i < 5; i++)
        o4[i] = make_float4(dv[4 * i], dv[4 * i + 1], dv[4 * i + 2], dv[4 * i + 3]);
}

// ---------------------------------------------------------------------------
extern "C" void kernel_launch(void* const* d_in, const int* in_sizes, int n_in,
                              void* d_out, int out_size)
{
    const float* features = (const float*)d_in[0];
    const int*   adj      = (const int*)d_in[1];
    const float* We1 = (const float*)d_in[2];  const float* be1 = (const float*)d_in[3];
    const float* We2 = (const float*)d_in[4];  const float* be2 = (const float*)d_in[5];
    const float* We3 = (const float*)d_in[6];  const float* be3 = (const float*)d_in[7];
    const float* Wd1 = (const float*)d_in[8];  const float* bd1 = (const float*)d_in[9];
    const float* Wd2 = (const float*)d_in[10]; const float* bd2 = (const float*)d_in[11];
    const float* Wd3 = (const float*)d_in[12]; const float* bd3 = (const float*)d_in[13];

    int N = in_sizes[0] / NODELEN;

    float* out = (float*)d_out;
    float* enc_out = out;                     // [N,5]
    float* dec_out = out + (size_t)N * 5;     // [N,20]
    float* emb_out = out + (size_t)N * 25;    // [N,20]

    int pad_blocks = (N * PAD + 255) / 256;
    pad_features_kernel<<<pad_blocks, 256>>>(features, N);

    int hop_blocks = (N + 7) / 8;   // one warp per node, 8 warps/block
    hop1_kernel<<<hop_blocks, 256>>>(adj, N);
    hop2_emb_kernel<<<hop_blocks, 256>>>(adj, emb_out, N);

    int mlp_blocks = (N + 127) / 128;
    mlp_kernel<<<mlp_blocks, 128>>>(emb_out,
                                    We1, be1, We2, be2, We3, be3,
                                    Wd1, bd1, Wd2, bd2, Wd3, bd3,
                                    enc_out, dec_out, N);
}

// round 3
// speedup vs baseline: 1.2200x; 1.2200x over previous
#include <cuda_runtime.h>
#include <cuda_fp16.h>

#define NODELEN 10
#define DEG 32
#define MAXN 200000
#define PADH 16   // halves per row: 32B = one sector, sector-aligned

// Allocation-free scratch: fp16 gather tables, one sector per row.
__device__ __half g_featH[(size_t)MAXN * PADH];
__device__ __half g_h1H[(size_t)MAXN * PADH];

// ---------------------------------------------------------------------------
// Pack: features [N,10] fp32 -> g_featH [N,16] fp16 (zero padded).
// ---------------------------------------------------------------------------
__global__ __launch_bounds__(256) void pack_features_kernel(
    const float* __restrict__ features, int N)
{
    int idx = blockIdx.x * blockDim.x + threadIdx.x;
    if (idx >= N * PADH) return;
    int n = idx >> 4;
    int k = idx & 15;
    float v = (k < NODELEN) ? features[(size_t)n * NODELEN + k] : 0.f;
    g_featH[idx] = __float2half_rn(v);
}

// ---------------------------------------------------------------------------
// Gather-mean core: one warp per node. Each gathered row = 16 halves = 32B =
// ONE sector. Lane l: r=l>>3 (row-in-group), j=l&7 (dim pair). 8 LDG.32 per
// node, 4 random rows per instruction. Butterfly-reduce over r.
// Returns: lanes 0..7 hold the 32-row SUM for dims (2j, 2j+1) in float2.
// ---------------------------------------------------------------------------
__device__ __forceinline__ float2 gather_sum16(const __half* __restrict__ tab,
                                               int myNb, int lane)
{
    int r = lane >> 3;   // 0..3
    int j = lane & 7;    // dim pair 0..7
    float2 acc = make_float2(0.f, 0.f);
#pragma unroll
    for (int i = 0; i < 8; i++) {
        int nb = __shfl_sync(0xffffffffu, myNb, 4 * i + r);
        __half2 h = *reinterpret_cast<const __half2*>(tab + (size_t)nb * PADH + 2 * j);
        float2 v = __half22float2(h);
        acc.x += v.x; acc.y += v.y;
    }
#pragma unroll
    for (int off = 8; off < 32; off <<= 1) {
        acc.x += __shfl_xor_sync(0xffffffffu, acc.x, off);
        acc.y += __shfl_xor_sync(0xffffffffu, acc.y, off);
    }
    return acc;
}

// ---------------------------------------------------------------------------
// Hop 1: h1 = mean(features[adj]), col 0 zeroed, stored fp16 padded.
// ---------------------------------------------------------------------------
__global__ __launch_bounds__(256) void hop1_kernel(
    const int* __restrict__ adj, int N)
{
    int warp = (blockIdx.x * blockDim.x + threadIdx.x) >> 5;
    int lane = threadIdx.x & 31;
    if (warp >= N) return;

    int myNb = adj[warp * DEG + lane];
    float2 s = gather_sum16(g_featH, myNb, lane);

    if (lane < 8) {
        float2 v;
        v.x = s.x * (1.f / 32.f);
        v.y = s.y * (1.f / 32.f);
        if (lane == 0) v.x = 0.f;            // h1[:,0] = 0
        __half2 h = __floats2half2_rn(v.x, v.y);
        *reinterpret_cast<__half2*>(g_h1H + (size_t)warp * PADH + 2 * lane) = h;
    }
}

// ---------------------------------------------------------------------------
// Hop 2 + emb: agg = mean(h1[adj]) (col0 zero);
// emb = [features fp32 (col0=0) | agg], written fp32 to d_out.
// ---------------------------------------------------------------------------
__global__ __launch_bounds__(256) void hop2_emb_kernel(
    const float* __restrict__ features, const int* __restrict__ adj,
    float* __restrict__ emb, int N)
{
    int warp = (blockIdx.x * blockDim.x + threadIdx.x) >> 5;
    int lane = threadIdx.x & 31;
    if (warp >= N) return;

    int myNb = adj[warp * DEG + lane];
    float2 s = gather_sum16(g_h1H, myNb, lane);

    float* row = emb + (size_t)warp * (2 * NODELEN);
    if (lane < 8) {
        // agg dims (2*lane, 2*lane+1) -> emb cols 10+2*lane (only lane<5 real)
        if (lane < 5) {
            float2 v;
            v.x = s.x * (1.f / 32.f);
            v.y = s.y * (1.f / 32.f);
            if (lane == 0) v.x = 0.f;        // emb[:,NODELEN] = 0
            *reinterpret_cast<float2*>(row + 10 + 2 * lane) = v;
        }
    } else if (lane < 8 + NODELEN) {
        // self features cols 0..9, col 0 zeroed (exact fp32 from input)
        int d = lane - 8;
        row[d] = (d == 0) ? 0.f : features[(size_t)warp * NODELEN + d];
    }
}

// ---------------------------------------------------------------------------
// MLP autoencoder: thread-per-node, weights in shared; emb tile and decoded
// tile staged through shared memory for fully coalesced global traffic.
// ---------------------------------------------------------------------------
#define MLP_BLK 256
#define EMB_PAD 21   // 20-float row padded to 21 (odd -> conflict-free LDS)

__global__ __launch_bounds__(MLP_BLK) void mlp_kernel(
    const float* __restrict__ emb,
    const float* __restrict__ We1, const float* __restrict__ be1,
    const float* __restrict__ We2, const float* __restrict__ be2,
    const float* __restrict__ We3, const float* __restrict__ be3,
    const float* __restrict__ Wd1, const float* __restrict__ bd1,
    const float* __restrict__ Wd2, const float* __restrict__ bd2,
    const float* __restrict__ Wd3, const float* __restrict__ bd3,
    float* __restrict__ enc_out, float* __restrict__ dec_out, int N)
{
    // weight layout (W blocks at 16B-aligned offsets)
    __shared__ float sw[1084];
    __shared__ float se[MLP_BLK * EMB_PAD];

    const int tid = threadIdx.x;
    {
        const float* srcs[12] = {We1, We2, We3, Wd1, Wd2, Wd3,
                                 be1, be2, be3, bd1, bd2, bd3};
        const int off[12] = {0, 300, 452, 504, 556, 708,
                             1008, 1023, 1033, 1038, 1048, 1063};
        const int sz[12]  = {300, 150, 50, 50, 150, 300,
                             15, 10, 5, 10, 15, 20};
#pragma unroll
        for (int a = 0; a < 12; a++)
            for (int k = tid; k < sz[a]; k += MLP_BLK)
                sw[off[a] + k] = srcs[a][k];
    }

    // stage emb tile: coalesced float4 loads (rows are 20 floats, 20%4==0)
    const int base = blockIdx.x * MLP_BLK;          // first node of tile
    const long f4base = (long)base * 5;             // float4 index of tile start
    const long f4total = (long)N * 5;
#pragma unroll
    for (int i = 0; i < 5; i++) {
        long f4 = f4base + tid + i * MLP_BLK;
        if (f4 < f4total) {
            float4 t = reinterpret_cast<const float4*>(emb)[f4];
            int lf4 = tid + i * MLP_BLK;            // local float4 idx
            int rrow = lf4 / 5, q = lf4 % 5;
            float* d = se + rrow * EMB_PAD + q * 4;
            d[0] = t.x; d[1] = t.y; d[2] = t.z; d[3] = t.w;
        }
    }
    __syncthreads();

    const int n = base + tid;
    const float* sWe1 = sw;        const float* sWe2 = sw + 300;
    const float* sWe3 = sw + 452;  const float* sWd1 = sw + 504;
    const float* sWd2 = sw + 556;  const float* sWd3 = sw + 708;
    const float* sbe1 = sw + 1008; const float* sbe2 = sw + 1023;
    const float* sbe3 = sw + 1033; const float* sbd1 = sw + 1038;
    const float* sbd2 = sw + 1048; const float* sbd3 = sw + 1063;

    if (n < N) {
        float x[20];
#pragma unroll
        for (int j = 0; j < 20; j++) x[j] = se[tid * EMB_PAD + j];

        float h1v[15];
#pragma unroll
        for (int i = 0; i < 15; i++) {
            float a = sbe1[i];
#pragma unroll
            for (int j = 0; j < 20; j++) a = fmaf(sWe1[i * 20 + j], x[j], a);
            h1v[i] = fmaxf(a, 0.f);
        }
        float h2v[10];
#pragma unroll
        for (int i = 0; i < 10; i++) {
            float a = sbe2[i];
#pragma unroll
            for (int j = 0; j < 15; j++) a = fmaf(sWe2[i * 15 + j], h1v[j], a);
            h2v[i] = fmaxf(a, 0.f);
        }
        float ev[5];
#pragma unroll
        for (int i = 0; i < 5; i++) {
            float a = sbe3[i];
#pragma unroll
            for (int j = 0; j < 10; j++) a = fmaf(sWe3[i * 10 + j], h2v[j], a);
            ev[i] = a;
        }
#pragma unroll
        for (int i = 0; i < 5; i++) enc_out[(size_t)n * 5 + i] = ev[i];

        float d1v[10];
#pragma unroll
        for (int i = 0; i < 10; i++) {
            float a = sbd1[i];
#pragma unroll
            for (int j = 0; j < 5; j++) a = fmaf(sWd1[i * 5 + j], ev[j], a);
            d1v[i] = fmaxf(a, 0.f);
        }
        float d2v[15];
#pragma unroll
        for (int i = 0; i < 15; i++) {
            float a = sbd2[i];
#pragma unroll
            for (int j = 0; j < 10; j++) a = fmaf(sWd2[i * 10 + j], d1v[j], a);
            d2v[i] = fmaxf(a, 0.f);
        }
        // decoded -> own row of se (each thread touches only its own row; the
        // earlier reads of this row were by this same thread, no sync needed)
#pragma unroll
        for (int i = 0; i < 20; i++) {
            float a = sbd3[i];
#pragma unroll
            for (int j = 0; j < 15; j++) a = fmaf(sWd3[i * 15 + j], d2v[j], a);
            se[tid * EMB_PAD + i] = a;
        }
    }
    __syncthreads();

    // coalesced float4 stores of decoded tile
#pragma unroll
    for (int i = 0; i < 5; i++) {
        long f4 = f4base + tid + i * MLP_BLK;
        if (f4 < f4total) {
            int lf4 = tid + i * MLP_BLK;
            int rrow = lf4 / 5, q = lf4 % 5;
            const float* s = se + rrow * EMB_PAD + q * 4;
            reinterpret_cast<float4*>(dec_out)[f4] =
                make_float4(s[0], s[1], s[2], s[3]);
        }
    }
}

// ---------------------------------------------------------------------------
extern "C" void kernel_launch(void* const* d_in, const int* in_sizes, int n_in,
                              void* d_out, int out_size)
{
    const float* features = (const float*)d_in[0];
    const int*   adj      = (const int*)d_in[1];
    const float* We1 = (const float*)d_in[2];  const float* be1 = (const float*)d_in[3];
    const float* We2 = (const float*)d_in[4];  const float* be2 = (const float*)d_in[5];
    const float* We3 = (const float*)d_in[6];  const float* be3 = (const float*)d_in[7];
    const float* Wd1 = (const float*)d_in[8];  const float* bd1 = (const float*)d_in[9];
    const float* Wd2 = (const float*)d_in[10]; const float* bd2 = (const float*)d_in[11];
    const float* Wd3 = (const float*)d_in[12]; const float* bd3 = (const float*)d_in[13];

    int N = in_sizes[0] / NODELEN;

    float* out = (float*)d_out;
    float* enc_out = out;                     // [N,5]
    float* dec_out = out + (size_t)N * 5;     // [N,20]
    float* emb_out = out + (size_t)N * 25;    // [N,20]

    int pack_blocks = (N * PADH + 255) / 256;
    pack_features_kernel<<<pack_blocks, 256>>>(features, N);

    int hop_blocks = (N + 7) / 8;   // one warp per node, 8 warps/block
    hop1_kernel<<<hop_blocks, 256>>>(adj, N);
    hop2_emb_kernel<<<hop_blocks, 256>>>(features, adj, emb_out, N);

    int mlp_blocks = (N + MLP_BLK - 1) / MLP_BLK;
    mlp_kernel<<<mlp_blocks, MLP_BLK>>>(emb_out,
                                        We1, be1, We2, be2, We3, be3,
                                        Wd1, bd1, Wd2, bd2, Wd3, bd3,
                                        enc_out, dec_out, N);
}